// round 6
// baseline (speedup 1.0000x reference)
#include <cuda_runtime.h>
#include <cuda_bf16.h>
#include <math.h>

#define BB 4
#define CC 256
#define NN 128
#define HH 200
#define WW 176
#define GG 7
#define GP 49
#define NW 4            /* warps per block */
#define THREADS 128
#define CSPLIT 8        /* blocks per ROI (channel split) */
#define CPB (CC / CSPLIT)   /* 32 channels per block */
#define TROWS 18        /* tile row capacity (max real span <= 16) */
#define TSMAX 28        /* max smem row stride (wb+4), floats */
#define TCAP (TROWS * TSMAX)
#define NBUF 3          /* cp.async pipeline stages */

__device__ __forceinline__ void cpa16(unsigned s, const void* g) {
    asm volatile("cp.async.cg.shared.global [%0], [%1], 16;" :: "r"(s), "l"(g));
}
__device__ __forceinline__ void cpa_commit() {
    asm volatile("cp.async.commit_group;");
}
__device__ __forceinline__ void cpa_wait2() {
    asm volatile("cp.async.wait_group 2;");
}

__global__ __launch_bounds__(THREADS, 8) void rotpool_kernel(
    const float* __restrict__ feat, const float* __restrict__ rois,
    const float* __restrict__ voxel, const int* __restrict__ stridep,
    float* __restrict__ out)
{
    __shared__ __align__(16) float tile[NBUF][NW][TCAP];
    __shared__ __align__(16) int4   poff[64];
    __shared__ __align__(16) float4 pwt[64];
    __shared__ int sxmin, sxmax, symin, symax;
    __shared__ int s_x0, s_y0, s_wb4, s_hb, s_ts, s_fits;

    const int tid  = threadIdx.x;
    const int lane = tid & 31;
    const int w    = tid >> 5;
    const int blk  = blockIdx.x;
    const int bn   = blk >> 3;             /* ROI index (0..511) */
    const int part = blk & 7;              /* channel slice */
    const int b    = bn >> 7;              /* batch */

    if (tid == 0) {
        sxmin = 1 << 30; symin = 1 << 30;
        sxmax = -(1 << 30); symax = -(1 << 30);
    }
    if (tid >= GP && tid < 64) {
        poff[tid] = make_int4(0, 0, 0, 0);
        pwt[tid]  = make_float4(0.f, 0.f, 0.f, 0.f);
    }
    __syncthreads();

    float ix = 0.f, iy = 0.f;
    if (tid < GP) {
        const float* roi = rois + (size_t)bn * 7;
        float fstride = (float)stridep[0];
        float vx = voxel[0] * fstride;
        float vy = voxel[1] * fstride;
        float cx = roi[0], cy = roi[1];
        float dx = roi[3], dy = roi[4];
        float ang = roi[6];
        float x1 = (cx - dx * 0.5f) / vx;
        float x2 = (cx + dx * 0.5f) / vx;
        float y1 = (cy - dy * 0.5f + 40.0f) / vy;
        float y2 = (cy + dy * 0.5f + 40.0f) / vy;
        float cosa = cosf(ang), sina = sinf(ang);
        float scale1 = (y2 - y1) / fmaxf(x2 - x1, 0.01f);
        float scale2 = (x2 - x1) / fmaxf(y2 - y1, 0.01f);
        float t00 = (x2 - x1) / (float)(WW - 1) * cosa;
        float t01 = (x2 - x1) / (float)(WW - 1) * (-sina) * scale1;
        float t02 = (x1 + x2 - (float)WW + 1.0f) / (float)(WW - 1);
        float t10 = (y2 - y1) / (float)(HH - 1) * sina * scale2;
        float t11 = (y2 - y1) / (float)(HH - 1) * cosa;
        float t12 = (y1 + y2 - (float)HH + 1.0f) / (float)(HH - 1);
        int r = tid / GG, q = tid - r * GG;
        float xx = (2.0f * (float)q + 1.0f) / (float)GG - 1.0f;
        float yy = (2.0f * (float)r + 1.0f) / (float)GG - 1.0f;
        float gx = t00 * xx + t01 * yy + t02;
        float gy = t10 * xx + t11 * yy + t12;
        ix = ((gx + 1.0f) * (float)WW - 1.0f) * 0.5f;
        iy = ((gy + 1.0f) * (float)HH - 1.0f) * 0.5f;
        float x0f = floorf(ix), y0f = floorf(iy);
        int x0c = (int)fminf(fmaxf(x0f,        0.0f), (float)(WW - 1));
        int x1c = (int)fminf(fmaxf(x0f + 1.0f, 0.0f), (float)(WW - 1));
        int y0c = (int)fminf(fmaxf(y0f,        0.0f), (float)(HH - 1));
        int y1c = (int)fminf(fmaxf(y0f + 1.0f, 0.0f), (float)(HH - 1));
        atomicMin(&sxmin, x0c); atomicMax(&sxmax, x1c);
        atomicMin(&symin, y0c); atomicMax(&symax, y1c);
    }
    __syncthreads();

    if (tid == 0) {
        int x0 = sxmin & ~7;
        int wb = ((sxmax - x0 + 1) + 7) & ~7;
        int hb = symax - symin + 1;
        int fits = (hb <= TROWS) && ((wb + 4) <= TSMAX);
        s_x0 = x0; s_y0 = symin;
        s_wb4 = wb >> 2;
        s_hb = hb;
        s_ts = wb + 4;
        s_fits = fits;
    }
    __syncthreads();
    const int fits = s_fits;
    const int x0 = s_x0, y0v = s_y0, wb4 = s_wb4, hb = s_hb, ts = s_ts;

    if (tid < GP) {
        float x0f = floorf(ix), y0f = floorf(iy);
        float wx1 = ix - x0f, wx0 = 1.0f - wx1;
        float wy1 = iy - y0f, wy0 = 1.0f - wy1;
        float x1f = x0f + 1.0f, y1f = y0f + 1.0f;
        float vx0 = (x0f >= 0.0f && x0f <= (float)(WW - 1)) ? 1.0f : 0.0f;
        float vx1 = (x1f >= 0.0f && x1f <= (float)(WW - 1)) ? 1.0f : 0.0f;
        float vy0 = (y0f >= 0.0f && y0f <= (float)(HH - 1)) ? 1.0f : 0.0f;
        float vy1 = (y1f >= 0.0f && y1f <= (float)(HH - 1)) ? 1.0f : 0.0f;
        int x0c = (int)fminf(fmaxf(x0f, 0.0f), (float)(WW - 1));
        int x1c = (int)fminf(fmaxf(x1f, 0.0f), (float)(WW - 1));
        int y0c = (int)fminf(fmaxf(y0f, 0.0f), (float)(HH - 1));
        int y1c = (int)fminf(fmaxf(y1f, 0.0f), (float)(HH - 1));
        int rs = fits ? ts : WW;
        int xo = fits ? x0 : 0;
        int yo = fits ? y0v : 0;
        int l0 = (y0c - yo) * rs + (x0c - xo);
        int sx = x1c - x0c;
        int sy = (y1c - y0c) * rs;
        poff[tid] = make_int4(l0, l0 + sx, l0 + sy, l0 + sy + sx);
        pwt[tid]  = make_float4(wy0 * wx0 * vy0 * vx0,
                                wy0 * wx1 * vy0 * vx1,
                                wy1 * wx0 * vy1 * vx0,
                                wy1 * wx1 * vy1 * vx1);
    }
    __syncthreads();

    /* channel-invariant gather params in registers */
    const int4   o0 = poff[lane];
    const float4 w0 = pwt[lane];
    const int4   o1 = poff[lane + 32];
    const float4 w1 = pwt[lane + 32];
    const bool   p1ok = (lane + 32) < GP;

    const size_t HWs = (size_t)HH * WW;
    const float* fb = feat + (size_t)b * CC * HWs;
    float* ob = out + (size_t)bn * CC * GP;
    const int cbeg = part * CPB + w;
    const int cend = part * CPB + CPB;

    if (fits) {
        const int total4 = hb * wb4;
        /* per-lane fixed addresses (<=4 float4 elements) */
        int goff[4]; unsigned sboff[4]; bool act[4];
        #pragma unroll
        for (int i = 0; i < 4; ++i) {
            int e = lane + 32 * i;
            act[i] = e < total4;
            int r = e / wb4;
            int col = e - r * wb4;
            goff[i]  = r * (WW / 4) + col;
            sboff[i] = (unsigned)((r * ts + col * 4) * 4);
        }
        unsigned sb[NBUF];
        #pragma unroll
        for (int i = 0; i < NBUF; ++i)
            sb[i] = (unsigned)__cvta_generic_to_shared(tile[i][w]);
        const float4* srcbase = (const float4*)(fb + (size_t)y0v * WW + x0);
        const size_t planestep4 = HWs >> 2;
        const size_t cstep = (size_t)NW * planestep4;

        /* prologue: stage channels cbeg, cbeg+NW into buffers 0,1 */
        const float4* srcP = srcbase + (size_t)cbeg * planestep4;
        {
            #pragma unroll
            for (int i = 0; i < 4; ++i)
                if (act[i]) cpa16(sb[0] + sboff[i], srcP + goff[i]);
            cpa_commit();
            srcP += cstep;
            if (cbeg + NW < cend) {
                #pragma unroll
                for (int i = 0; i < 4; ++i)
                    if (act[i]) cpa16(sb[1] + sboff[i], srcP + goff[i]);
            }
            cpa_commit();
            srcP += cstep;
        }

        int p = 0;
        float* od = ob + (size_t)cbeg * GP;
        #pragma unroll 1
        for (int c = cbeg; c < cend; c += NW) {
            /* stage channel c + 2*NW into buffer (p+2)%NBUF */
            if (c + 2 * NW < cend) {
                int pn = p + 2; if (pn >= NBUF) pn -= NBUF;
                #pragma unroll
                for (int i = 0; i < 4; ++i)
                    if (act[i]) cpa16(sb[pn] + sboff[i], srcP + goff[i]);
            }
            cpa_commit();
            srcP += cstep;
            cpa_wait2();          /* oldest group (channel c) resident */
            __syncwarp();

            const float* tc = tile[p][w];
            float v0 = w0.x * tc[o0.x] + w0.y * tc[o0.y]
                     + w0.z * tc[o0.z] + w0.w * tc[o0.w];
            od[lane] = v0;
            if (p1ok) {
                float v1 = w1.x * tc[o1.x] + w1.y * tc[o1.y]
                         + w1.z * tc[o1.z] + w1.w * tc[o1.w];
                od[lane + 32] = v1;
            }
            __syncwarp();
            od += (size_t)NW * GP;
            if (++p >= NBUF) p = 0;
        }
    } else {
        /* unreachable with these input ranges; direct gmem gather */
        #pragma unroll 1
        for (int c = cbeg; c < cend; c += NW) {
            const float* plane = fb + (size_t)c * HWs;
            float v0 = w0.x * __ldg(plane + o0.x) + w0.y * __ldg(plane + o0.y)
                     + w0.z * __ldg(plane + o0.z) + w0.w * __ldg(plane + o0.w);
            float* od = ob + (size_t)c * GP;
            od[lane] = v0;
            if (p1ok) {
                float v1 = w1.x * __ldg(plane + o1.x) + w1.y * __ldg(plane + o1.y)
                         + w1.z * __ldg(plane + o1.z) + w1.w * __ldg(plane + o1.w);
                od[lane + 32] = v1;
            }
        }
    }
}

extern "C" void kernel_launch(void* const* d_in, const int* in_sizes, int n_in,
                              void* d_out, int out_size)
{
    const float* feat   = (const float*)d_in[0];
    const float* rois   = (const float*)d_in[1];
    const float* voxel  = (const float*)d_in[2];
    const int*   stride = (const int*)d_in[3];
    float* out = (float*)d_out;
    (void)in_sizes; (void)n_in; (void)out_size;
    rotpool_kernel<<<BB * NN * CSPLIT, THREADS>>>(feat, rois, voxel, stride, out);
}